// round 14
// baseline (speedup 1.0000x reference)
#include <cuda_runtime.h>
#include <math.h>
#include <cstdint>

#define Bsz   2
#define Sq    2048
#define Dm    1024
#define Hh    16
#define Mtot  4096
#define DIMq  256
#define EPSf  1e-5f
#define LOG2E 1.44269504088896f

// ---------------- scratch ----------------
__device__ uint32_t g_xp[Mtot * 512];
__device__ uint32_t g_wp[4 * 1024 * 512];
__device__ uint32_t g_qp[Mtot * 512];
__device__ uint32_t g_kp[Mtot * 512];
__device__ float    g_v [Mtot * Dm];
__device__ uint32_t g_vt[Mtot * 512];
__device__ uint32_t g_op[Mtot * 512];
__device__ float    g_proj[Mtot * Dm];

// ======================= helpers =======================
__device__ __forceinline__ uint32_t smem_to_u32(const void* p) {
    uint32_t a;
    asm("{ .reg .u64 t; cvta.to.shared.u64 t, %1; cvt.u32.u64 %0, t; }" : "=r"(a) : "l"(p));
    return a;
}
__device__ __forceinline__ void cp16(uint32_t sm, const void* g) {
    asm volatile("cp.async.cg.shared.global [%0], [%1], 16;" :: "r"(sm), "l"(g));
}
__device__ __forceinline__ void cp_commit() {
    asm volatile("cp.async.commit_group;");
}
template <int N>
__device__ __forceinline__ void cp_wait() {
    asm volatile("cp.async.wait_group %0;" :: "n"(N));
}
__device__ __forceinline__ uint32_t f2bf2(float lo, float hi) {
    uint32_t r;
    asm("cvt.rn.bf16x2.f32 %0, %1, %2;" : "=r"(r) : "f"(hi), "f"(lo));
    return r;
}
__device__ __forceinline__ void mma_bf16(float c[4], const uint32_t a[4], const uint32_t b[2]) {
    asm volatile(
        "mma.sync.aligned.m16n8k16.row.col.f32.bf16.bf16.f32 "
        "{%0,%1,%2,%3}, {%4,%5,%6,%7}, {%8,%9}, {%0,%1,%2,%3};"
        : "+f"(c[0]), "+f"(c[1]), "+f"(c[2]), "+f"(c[3])
        : "r"(a[0]), "r"(a[1]), "r"(a[2]), "r"(a[3]), "r"(b[0]), "r"(b[1]));
}

// ================= pack x -> bf16x2 =================
__global__ __launch_bounds__(256) void pack_x(const float4* __restrict__ x4,
                                              uint4* __restrict__ xp4)
{
    int idx = blockIdx.x * 256 + threadIdx.x;
    float4 a = x4[idx * 2];
    float4 b = x4[idx * 2 + 1];
    uint4 w;
    w.x = f2bf2(a.x, a.y); w.y = f2bf2(a.z, a.w);
    w.z = f2bf2(b.x, b.y); w.w = f2bf2(b.z, b.w);
    xp4[idx] = w;
}

// ================= pack 4 weights -> bf16x2 =================
__global__ __launch_bounds__(256) void pack_w(const float* __restrict__ W0,
                                              const float* __restrict__ W1,
                                              const float* __restrict__ W2,
                                              const float* __restrict__ W3,
                                              uint32_t* __restrict__ wp)
{
    const int z = blockIdx.y;
    const float* W = (z == 0) ? W0 : (z == 1) ? W1 : (z == 2) ? W2 : W3;
    const float4* w4 = reinterpret_cast<const float4*>(W);
    uint4* o4 = reinterpret_cast<uint4*>(wp + (size_t)z * 1024 * 512);
    int idx = blockIdx.x * 256 + threadIdx.x;
    float4 a = w4[idx * 2];
    float4 b = w4[idx * 2 + 1];
    uint4 w;
    w.x = f2bf2(a.x, a.y); w.y = f2bf2(a.z, a.w);
    w.z = f2bf2(b.x, b.y); w.w = f2bf2(b.z, b.w);
    o4[idx] = w;
}

// ======= V transpose+pack =======
__global__ __launch_bounds__(256) void vtrans(const float* __restrict__ v,
                                              uint32_t* __restrict__ vt)
{
    __shared__ float sm[64 * 65 + 16];
    const int tid = threadIdx.x;
    const int kt = blockIdx.x, h = blockIdx.y, b = blockIdx.z;
    const float* vg = v + (size_t)(b * Sq + kt * 64) * 1024 + h * 64;

#pragma unroll
    for (int i = 0; i < 4; i++) {
        int e = tid + (i << 8);
        int r = e >> 4, c4 = (e & 15) << 2;
        float4 vv = *reinterpret_cast<const float4*>(vg + (size_t)r * 1024 + c4);
        sm[(c4 + 0) * 65 + r] = vv.x;
        sm[(c4 + 1) * 65 + r] = vv.y;
        sm[(c4 + 2) * 65 + r] = vv.z;
        sm[(c4 + 3) * 65 + r] = vv.w;
    }
    __syncthreads();

    uint32_t* og = vt + ((size_t)(b * Hh + h) * 64) * 1024 + kt * 32;
#pragma unroll
    for (int i = 0; i < 8; i++) {
        int idx = tid + (i << 8);
        int d = idx >> 5, kp = idx & 31;
        og[(size_t)d * 1024 + kp] = f2bf2(sm[d * 65 + 2 * kp], sm[d * 65 + 2 * kp + 1]);
    }
}

// ============ bf16 GEMM, BOTH operands packed (R13-proven) ============
#define BM 128
#define BN 256
#define PAW 20
#define PBW 20
#define PA_STAGE_B (BM * PAW * 4)
#define PB_STAGE_B (BN * PBW * 4)
#define GPSMEM (3 * (PA_STAGE_B + PB_STAGE_B))
#define NKT (Dm / 32)

__device__ __forceinline__ void gemm_pp(const uint32_t* __restrict__ Ap,
                                        const uint32_t* __restrict__ Wp,
                                        float* __restrict__ Cf,
                                        uint32_t* __restrict__ Cp,
                                        int outmode, float scale,
                                        char* gsm)
{
    const uint32_t usm = smem_to_u32(gsm);
    const uint32_t usmA = usm;
    const uint32_t usmB = usm + 3 * PA_STAGE_B;

    const int tid  = threadIdx.x;
    const int wid  = tid >> 5;
    const int lane = tid & 31;
    const int grp  = lane >> 2;
    const int tig  = lane & 3;
    const int wm   = wid >> 2;
    const int wn   = wid & 3;

    const int aRow0 = blockIdx.y * BM;
    const int bRow0 = blockIdx.x * BN;

    int aSm[2], aGm[2], bSm[4], bGm[4];
#pragma unroll
    for (int i = 0; i < 2; i++) {
        int e = tid + (i << 8);
        int r = e >> 2, c4 = (e & 3) << 2;
        aSm[i] = (r * PAW + c4) * 4;
        aGm[i] = r * 512 + c4;
    }
#pragma unroll
    for (int i = 0; i < 4; i++) {
        int e = tid + (i << 8);
        int r = e >> 2, c4 = (e & 3) << 2;
        bSm[i] = (r * PBW + c4) * 4;
        bGm[i] = r * 512 + c4;
    }
    const uint32_t* gA = Ap + (size_t)aRow0 * 512;
    const uint32_t* gB = Wp + (size_t)bRow0 * 512;

    float acc[4][8][4];
#pragma unroll
    for (int im = 0; im < 4; im++)
#pragma unroll
        for (int jn = 0; jn < 8; jn++)
#pragma unroll
            for (int t = 0; t < 4; t++) acc[im][jn][t] = 0.f;

#pragma unroll
    for (int p = 0; p < 2; p++) {
        uint32_t sa = usmA + p * PA_STAGE_B;
        uint32_t sb = usmB + p * PB_STAGE_B;
        const uint32_t* ka = gA + p * 16;
        const uint32_t* kb = gB + p * 16;
#pragma unroll
        for (int i = 0; i < 2; i++) cp16(sa + aSm[i], ka + aGm[i]);
#pragma unroll
        for (int i = 0; i < 4; i++) cp16(sb + bSm[i], kb + bGm[i]);
        cp_commit();
    }

    for (int kt = 0; kt < NKT; kt++) {
        cp_wait<1>();
        __syncthreads();

        if (kt + 2 < NKT) {
            int s = (kt + 2) % 3;
            uint32_t sa = usmA + s * PA_STAGE_B;
            uint32_t sb = usmB + s * PB_STAGE_B;
            const uint32_t* ka = gA + (kt + 2) * 16;
            const uint32_t* kb = gB + (kt + 2) * 16;
#pragma unroll
            for (int i = 0; i < 2; i++) cp16(sa + aSm[i], ka + aGm[i]);
#pragma unroll
            for (int i = 0; i < 4; i++) cp16(sb + bSm[i], kb + bGm[i]);
        }
        cp_commit();

        const uint32_t* Asp = (const uint32_t*)(gsm + (kt % 3) * PA_STAGE_B);
        const uint32_t* Bsp = (const uint32_t*)(gsm + 3 * PA_STAGE_B + (kt % 3) * PB_STAGE_B);

#pragma unroll
        for (int k16 = 0; k16 < 2; k16++) {
            const int pi = k16 * 8 + tig;
            uint32_t afr[4][4], bfr[8][2];
#pragma unroll
            for (int im = 0; im < 4; im++) {
                int row = wm * 64 + im * 16 + grp;
                afr[im][0] = Asp[row * PAW + pi];
                afr[im][1] = Asp[(row + 8) * PAW + pi];
                afr[im][2] = Asp[row * PAW + pi + 4];
                afr[im][3] = Asp[(row + 8) * PAW + pi + 4];
            }
#pragma unroll
            for (int jn = 0; jn < 8; jn++) {
                int brow = wn * 64 + jn * 8 + grp;
                bfr[jn][0] = Bsp[brow * PBW + pi];
                bfr[jn][1] = Bsp[brow * PBW + pi + 4];
            }
#pragma unroll
            for (int im = 0; im < 4; im++)
#pragma unroll
                for (int jn = 0; jn < 8; jn++)
                    mma_bf16(acc[im][jn], afr[im], bfr[jn]);
        }
    }

    const int rowBase = aRow0 + wm * 64;
    const int colBase = bRow0 + wn * 64;
    if (outmode == 0) {
#pragma unroll
        for (int im = 0; im < 4; im++) {
            int r0 = rowBase + im * 16 + grp;
#pragma unroll
            for (int jn = 0; jn < 8; jn++) {
                int col = colBase + jn * 8 + 2 * tig;
                float2 v01 = make_float2(acc[im][jn][0], acc[im][jn][1]);
                float2 v23 = make_float2(acc[im][jn][2], acc[im][jn][3]);
                *reinterpret_cast<float2*>(Cf + (size_t)r0 * Dm + col) = v01;
                *reinterpret_cast<float2*>(Cf + (size_t)(r0 + 8) * Dm + col) = v23;
            }
        }
    } else {
#pragma unroll
        for (int im = 0; im < 4; im++) {
            int r0 = rowBase + im * 16 + grp;
#pragma unroll
            for (int jn = 0; jn < 8; jn++) {
                int col = colBase + jn * 8 + 2 * tig;
                Cp[(size_t)r0 * 512 + (col >> 1)] =
                    f2bf2(acc[im][jn][0] * scale, acc[im][jn][1] * scale);
                Cp[(size_t)(r0 + 8) * 512 + (col >> 1)] =
                    f2bf2(acc[im][jn][2] * scale, acc[im][jn][3] * scale);
            }
        }
    }
}

__global__ __launch_bounds__(256, 1) void gemm_qkv(const uint32_t* __restrict__ Ap,
                                                   const uint32_t* __restrict__ Wp,
                                                   uint32_t* __restrict__ Qp,
                                                   uint32_t* __restrict__ Kp,
                                                   float* __restrict__ Vf)
{
    extern __shared__ __align__(16) char gsm[];
    const int z = blockIdx.z;
    if (z == 0)      gemm_pp(Ap, Wp,               nullptr, Qp, 1, 0.125f * LOG2E, gsm);
    else if (z == 1) gemm_pp(Ap, Wp + 1024 * 512,  nullptr, Kp, 1, 1.f, gsm);
    else             gemm_pp(Ap, Wp + 2 * 1024 * 512, Vf, nullptr, 0, 1.f, gsm);
}

__global__ __launch_bounds__(256, 1) void gemm_wo(const uint32_t* __restrict__ Ap,
                                                  const uint32_t* __restrict__ Wp,
                                                  float* __restrict__ C)
{
    extern __shared__ __align__(16) char gsm[];
    gemm_pp(Ap, Wp + 3 * 1024 * 512, C, nullptr, 0, 1.f, gsm);
}

// ============ Flash attention: 128 Q rows/CTA, 16 rows/warp, 2 CTAs/SM ======
// smem (u32): Qp 128x36 | Pp 128x36 | Kp 3x64x36 | Vp 3x64x36 = 23040 u32 = 92160 B
#define PPW   36
#define KPW   36
#define QP_OFF 0
#define PP_OFF (128 * PPW)                   // 4608
#define KP_OFF (2 * 128 * PPW)               // 9216
#define KP_STRIDE (64 * KPW)                 // 2304
#define VP_OFF (KP_OFF + 3 * KP_STRIDE)      // 16128
#define FA_SMEM ((VP_OFF + 3 * KP_STRIDE) * 4)  // 92160 B
#define NKV (Sq / 64)

__global__ __launch_bounds__(256, 2) void flash_mma(const uint32_t* __restrict__ qpg,
                                                    const uint32_t* __restrict__ kpg,
                                                    const uint32_t* __restrict__ vtg_all,
                                                    uint32_t* __restrict__ op)
{
    extern __shared__ __align__(16) uint32_t fsu[];
    const uint32_t usm = smem_to_u32(fsu);
    uint32_t* qp = fsu + QP_OFF;
    uint32_t* pp = fsu + PP_OFF;
    const uint32_t* kp = fsu + KP_OFF;
    const uint32_t* vp = fsu + VP_OFF;

    const int tid  = threadIdx.x;
    const int wid  = tid >> 5;
    const int lane = tid & 31;
    const int grp  = lane >> 2;
    const int tig  = lane & 3;

    const int b  = blockIdx.z;
    const int h  = blockIdx.y;
    const int q0 = blockIdx.x << 7;          // 128 Q rows per CTA

    const uint32_t* qg  = qpg + (size_t)(b * Sq + q0) * 512 + h * 32;
    const uint32_t* kg  = kpg + (size_t)(b * Sq) * 512 + h * 32;
    const uint32_t* vtg = vtg_all + ((size_t)(b * Hh + h) * 64) * 1024;

    // ---- prologue: {K0,V0,Q} group0; {K1,V1} group1 ----
    {
#pragma unroll
        for (int i = 0; i < 2; i++) {
            int e = tid + (i << 8);
            int r = e >> 3, c4 = (e & 7) << 2;
            cp16(usm + (KP_OFF + r * KPW + c4) * 4, kg + (size_t)r * 512 + c4);
            cp16(usm + (VP_OFF + r * KPW + c4) * 4, vtg + (size_t)r * 1024 + c4);
        }
#pragma unroll
        for (int i = 0; i < 4; i++) {         // Q: 128 rows x 32 u32 = 4096 chunks/4
            int e = tid + (i << 8);
            int r = e >> 3, c4 = (e & 7) << 2;
            cp16(usm + (QP_OFF + r * PPW + c4) * 4, qg + (size_t)r * 512 + c4);
        }
        cp_commit();
#pragma unroll
        for (int i = 0; i < 2; i++) {
            int e = tid + (i << 8);
            int r = e >> 3, c4 = (e & 7) << 2;
            cp16(usm + (KP_OFF + KP_STRIDE + r * KPW + c4) * 4, kg + (size_t)(64 + r) * 512 + c4);
            cp16(usm + (VP_OFF + KP_STRIDE + r * KPW + c4) * 4, vtg + (size_t)r * 1024 + 32 + c4);
        }
        cp_commit();
    }

    const int lr0 = wid * 16 + grp;

    float m0 = -1e30f, m1 = -1e30f, l0 = 0.f, l1 = 0.f;
    float oac[8][4];
#pragma unroll
    for (int jd = 0; jd < 8; jd++)
#pragma unroll
        for (int t = 0; t < 4; t++) oac[jd][t] = 0.f;

    for (int it = 0; it < NKV; it++) {
        cp_wait<1>();
        __syncthreads();

        if (it + 2 < NKV) {
            int s = (it + 2) % 3;
            int kv0 = (it + 2) << 6;
            int kv32 = (it + 2) << 5;
#pragma unroll
            for (int i = 0; i < 2; i++) {
                int e = tid + (i << 8);
                int r = e >> 3, c4 = (e & 7) << 2;
                cp16(usm + (KP_OFF + s * KP_STRIDE + r * KPW + c4) * 4,
                     kg + (size_t)(kv0 + r) * 512 + c4);
                cp16(usm + (VP_OFF + s * KP_STRIDE + r * KPW + c4) * 4,
                     vtg + (size_t)r * 1024 + kv32 + c4);
            }
        }
        cp_commit();

        const uint32_t* Kb = kp + (it % 3) * KP_STRIDE;
        const uint32_t* Vb = vp + (it % 3) * KP_STRIDE;

        // ---- S = Q K^T ----
        float sac[8][4];
#pragma unroll
        for (int jn = 0; jn < 8; jn++)
#pragma unroll
            for (int t = 0; t < 4; t++) sac[jn][t] = 0.f;
#pragma unroll
        for (int k16 = 0; k16 < 4; k16++) {
            const int pi = k16 * 8 + tig;
            uint32_t af[4];
            af[0] = qp[lr0 * PPW + pi];       af[1] = qp[(lr0 + 8) * PPW + pi];
            af[2] = qp[lr0 * PPW + pi + 4];   af[3] = qp[(lr0 + 8) * PPW + pi + 4];
#pragma unroll
            for (int jn = 0; jn < 8; jn++) {
                int krow = jn * 8 + grp;
                uint32_t bfr[2];
                bfr[0] = Kb[krow * KPW + pi];
                bfr[1] = Kb[krow * KPW + pi + 4];
                mma_bf16(sac[jn], af, bfr);
            }
        }

        // ---- online softmax ----
        {
            float mx0 = -1e30f, mx1 = -1e30f;
#pragma unroll
            for (int jn = 0; jn < 8; jn++) {
                mx0 = fmaxf(mx0, fmaxf(sac[jn][0], sac[jn][1]));
                mx1 = fmaxf(mx1, fmaxf(sac[jn][2], sac[jn][3]));
            }
            mx0 = fmaxf(mx0, __shfl_xor_sync(0xffffffffu, mx0, 1));
            mx0 = fmaxf(mx0, __shfl_xor_sync(0xffffffffu, mx0, 2));
            mx1 = fmaxf(mx1, __shfl_xor_sync(0xffffffffu, mx1, 1));
            mx1 = fmaxf(mx1, __shfl_xor_sync(0xffffffffu, mx1, 2));
            float mn0 = fmaxf(m0, mx0), mn1 = fmaxf(m1, mx1);
            float al0 = exp2f(m0 - mn0), al1 = exp2f(m1 - mn1);
            float sum0 = 0.f, sum1 = 0.f;
#pragma unroll
            for (int jn = 0; jn < 8; jn++) {
                float p00 = exp2f(sac[jn][0] - mn0);
                float p01 = exp2f(sac[jn][1] - mn0);
                float p10 = exp2f(sac[jn][2] - mn1);
                float p11 = exp2f(sac[jn][3] - mn1);
                int ci = jn * 4 + tig;
                pp[lr0 * PPW + ci]       = f2bf2(p00, p01);
                pp[(lr0 + 8) * PPW + ci] = f2bf2(p10, p11);
                sum0 += p00 + p01;  sum1 += p10 + p11;
            }
            sum0 += __shfl_xor_sync(0xffffffffu, sum0, 1);
            sum0 += __shfl_xor_sync(0xffffffffu, sum0, 2);
            sum1 += __shfl_xor_sync(0xffffffffu, sum1, 1);
            sum1 += __shfl_xor_sync(0xffffffffu, sum1, 2);
            l0 = l0 * al0 + sum0;  m0 = mn0;
            l1 = l1 * al1 + sum1;  m1 = mn1;
#pragma unroll
            for (int jd = 0; jd < 8; jd++) {
                oac[jd][0] *= al0; oac[jd][1] *= al0;
                oac[jd][2] *= al1; oac[jd][3] *= al1;
            }
        }
        __syncwarp();

        // ---- O += P V ----
#pragma unroll
        for (int k16 = 0; k16 < 4; k16++) {
            const int pi = k16 * 8 + tig;
            uint32_t af[4];
            af[0] = pp[lr0 * PPW + pi];       af[1] = pp[(lr0 + 8) * PPW + pi];
            af[2] = pp[lr0 * PPW + pi + 4];   af[3] = pp[(lr0 + 8) * PPW + pi + 4];
#pragma unroll
            for (int jd = 0; jd < 8; jd++) {
                int dcol = jd * 8 + grp;
                uint32_t bfr[2];
                bfr[0] = Vb[dcol * KPW + pi];
                bfr[1] = Vb[dcol * KPW + pi + 4];
                mma_bf16(oac[jd], af, bfr);
            }
        }
    }

    // ---- epilogue: packed bf16x2 output ----
    {
        float inv0 = 1.f / l0, inv1 = 1.f / l1;
        uint32_t* og  = op + (size_t)(b * Sq + q0 + lr0) * 512 + h * 32;
        uint32_t* og8 = og + (size_t)8 * 512;
#pragma unroll
        for (int jd = 0; jd < 8; jd++) {
            og[jd * 4 + tig]  = f2bf2(oac[jd][0] * inv0, oac[jd][1] * inv0);
            og8[jd * 4 + tig] = f2bf2(oac[jd][2] * inv1, oac[jd][3] * inv1);
        }
    }
}

// ========= fused LN1 + quantum FFN + LN2 (R11-proven) =========
__global__ __launch_bounds__(256) void ln_quantum(const float* __restrict__ x,
                                                  const float* __restrict__ proj,
                                                  const float* __restrict__ g1,
                                                  const float* __restrict__ b1,
                                                  const float* __restrict__ Win,
                                                  const float* __restrict__ b_in,
                                                  const float* __restrict__ Wout,
                                                  const float* __restrict__ b_out,
                                                  const float* __restrict__ ry,
                                                  const float* __restrict__ g2,
                                                  const float* __restrict__ b2,
                                                  float* __restrict__ out)
{
    const int row = blockIdx.x;
    const int tid = threadIdx.x;
    const int lane = tid & 31, wid = tid >> 5;
    const float* px = x + (size_t)row * Dm;
    const float* pprj = proj + (size_t)row * Dm;

    __shared__ float redw[64];
    __shared__ float angs[8];
    __shared__ float ezs[8];
    __shared__ float2 st[2][DIMq];

    float xv[4];
    {
        float yv[4], sum = 0.f, sq = 0.f;
#pragma unroll
        for (int j = 0; j < 4; j++) {
            int d = tid + (j << 8);
            float t = px[d] + pprj[d];
            yv[j] = t; sum += t; sq = fmaf(t, t, sq);
        }
#pragma unroll
        for (int off = 16; off; off >>= 1) {
            sum += __shfl_xor_sync(0xffffffffu, sum, off);
            sq  += __shfl_xor_sync(0xffffffffu, sq, off);
        }
        if (lane == 0) { redw[wid] = sum; redw[8 + wid] = sq; }
        __syncthreads();
        float tsum = 0.f, tsq = 0.f;
#pragma unroll
        for (int w = 0; w < 8; w++) { tsum += redw[w]; tsq += redw[8 + w]; }
        float mean = tsum * (1.f / 1024.f);
        float var  = tsq * (1.f / 1024.f) - mean * mean;
        float rstd = rsqrtf(var + EPSf);
#pragma unroll
        for (int j = 0; j < 4; j++) {
            int d = tid + (j << 8);
            xv[j] = (yv[j] - mean) * rstd * g1[d] + b1[d];
        }
        __syncthreads();
    }

    float accq[8] = {0, 0, 0, 0, 0, 0, 0, 0};
#pragma unroll
    for (int j = 0; j < 4; j++) {
        int d = tid + (j << 8);
#pragma unroll
        for (int qq = 0; qq < 8; qq++)
            accq[qq] = fmaf(xv[j], Win[qq * Dm + d], accq[qq]);
    }
#pragma unroll
    for (int qq = 0; qq < 8; qq++) {
        float vsum = accq[qq];
#pragma unroll
        for (int off = 16; off; off >>= 1)
            vsum += __shfl_xor_sync(0xffffffffu, vsum, off);
        if (lane == 0) redw[wid * 8 + qq] = vsum;
    }
    __syncthreads();
    if (tid < 8) {
        float s = b_in[tid];
#pragma unroll
        for (int w = 0; w < 8; w++) s += redw[w * 8 + tid];
        angs[tid] = s * 0.5f;
    }
    st[0][tid] = make_float2(tid == 0 ? 1.f : 0.f, 0.f);
    __syncthreads();

    int curb = 0;
#pragma unroll
    for (int k = 0; k < 4; k++) {
        int m1 = 1 << (7 - 2 * k);
        int m2 = m1 >> 1;
        float s1, c1, s2, c2;
        __sincosf(angs[2 * k], &s1, &c1);
        __sincosf(angs[2 * k + 1], &s2, &c2);
        float cc = c1 * c2, cs = c1 * s2, sc = s1 * c2, ss = s1 * s2;
        float2 x0  = st[curb][tid];
        float2 x1  = st[curb][tid ^ m1];
        float2 x2  = st[curb][tid ^ m2];
        float2 x12 = st[curb][tid ^ (m1 | m2)];
        float nr = cc * x0.x + cs * x2.y + sc * x1.y - ss * x12.x;
        float ni = cc * x0.y - cs * x2.x - sc * x1.x - ss * x12.y;
        st[curb ^ 1][tid] = make_float2(nr, ni);
        curb ^= 1;
        __syncthreads();
    }
#pragma unroll
    for (int k = 0; k < 4; k++) {
        int m1 = 1 << (7 - 2 * k);
        int m2 = m1 >> 1;
        float s1, c1, s2, c2;
        __sincosf(ry[2 * k] * 0.5f, &s1, &c1);
        __sincosf(ry[2 * k + 1] * 0.5f, &s2, &c2);
        float sg1 = (tid & m1) ? s1 : -s1;
        float sg2 = (tid & m2) ? s2 : -s2;
        float cc = c1 * c2, a2 = c1 * sg2, a1 = sg1 * c2, a12 = sg1 * sg2;
        float2 x0  = st[curb][tid];
        float2 x1  = st[curb][tid ^ m1];
        float2 x2  = st[curb][tid ^ m2];
        float2 x12 = st[curb][tid ^ (m1 | m2)];
        float nr = cc * x0.x + a2 * x2.x + a1 * x1.x + a12 * x12.x;
        float ni = cc * x0.y + a2 * x2.y + a1 * x1.y + a12 * x12.y;
        st[curb ^ 1][tid] = make_float2(nr, ni);
        curb ^= 1;
        __syncthreads();
    }
    int src = tid;
#pragma unroll
    for (int c = 6; c >= 0; c--) {
        int cmask = 1 << (7 - c);
        int tmask = cmask >> 1;
        if (src & cmask) src ^= tmask;
    }
    float2 fa = st[curb][src];
    float p = fa.x * fa.x + fa.y * fa.y;

#pragma unroll
    for (int w = 0; w < 8; w++) {
        float vsum = ((tid >> (7 - w)) & 1) ? -p : p;
#pragma unroll
        for (int off = 16; off; off >>= 1)
            vsum += __shfl_xor_sync(0xffffffffu, vsum, off);
        if (lane == 0) redw[wid * 8 + w] = vsum;
    }
    __syncthreads();
    if (tid < 8) {
        float s = 0.f;
#pragma unroll
        for (int w = 0; w < 8; w++) s += redw[w * 8 + tid];
        ezs[tid] = s;
    }
    __syncthreads();
    float e[8];
#pragma unroll
    for (int qq = 0; qq < 8; qq++) e[qq] = ezs[qq];

    float y[4], sum = 0.f, sq = 0.f;
#pragma unroll
    for (int j = 0; j < 4; j++) {
        int d = tid + (j << 8);
        const float4* wrow = reinterpret_cast<const float4*>(Wout + (size_t)d * 8);
        float4 w0 = wrow[0], w1 = wrow[1];
        float acc = b_out[d];
        acc = fmaf(e[0], w0.x, acc); acc = fmaf(e[1], w0.y, acc);
        acc = fmaf(e[2], w0.z, acc); acc = fmaf(e[3], w0.w, acc);
        acc = fmaf(e[4], w1.x, acc); acc = fmaf(e[5], w1.y, acc);
        acc = fmaf(e[6], w1.z, acc); acc = fmaf(e[7], w1.w, acc);
        acc = fmaxf(acc, 0.f);
        float yv = xv[j] + acc;
        y[j] = yv; sum += yv; sq = fmaf(yv, yv, sq);
    }
    __syncthreads();
#pragma unroll
    for (int off = 16; off; off >>= 1) {
        sum += __shfl_xor_sync(0xffffffffu, sum, off);
        sq  += __shfl_xor_sync(0xffffffffu, sq, off);
    }
    if (lane == 0) { redw[wid] = sum; redw[8 + wid] = sq; }
    __syncthreads();
    float tsum = 0.f, tsq = 0.f;
#pragma unroll
    for (int w = 0; w < 8; w++) { tsum += redw[w]; tsq += redw[8 + w]; }
    float mean = tsum * (1.f / 1024.f);
    float var  = tsq * (1.f / 1024.f) - mean * mean;
    float rstd = rsqrtf(var + EPSf);
#pragma unroll
    for (int j = 0; j < 4; j++) {
        int d = tid + (j << 8);
        out[(size_t)row * Dm + d] = (y[j] - mean) * rstd * g2[d] + b2[d];
    }
}

// ---------------- launch ----------------
extern "C" void kernel_launch(void* const* d_in, const int* in_sizes, int n_in,
                              void* d_out, int out_size)
{
    const float* x     = (const float*)d_in[0];
    const float* Wq    = (const float*)d_in[1];
    const float* Wk    = (const float*)d_in[2];
    const float* Wv    = (const float*)d_in[3];
    const float* Wo    = (const float*)d_in[4];
    const float* g1    = (const float*)d_in[5];
    const float* b1    = (const float*)d_in[6];
    const float* g2    = (const float*)d_in[7];
    const float* b2    = (const float*)d_in[8];
    const float* Win   = (const float*)d_in[9];
    const float* b_in  = (const float*)d_in[10];
    const float* Wout  = (const float*)d_in[11];
    const float* b_out = (const float*)d_in[12];
    const float* ry    = (const float*)d_in[13];
    float* out = (float*)d_out;

    uint32_t *xp, *wp, *qp, *kp, *vt, *op;
    float *v, *proj;
    cudaGetSymbolAddress((void**)&xp,   g_xp);
    cudaGetSymbolAddress((void**)&wp,   g_wp);
    cudaGetSymbolAddress((void**)&qp,   g_qp);
    cudaGetSymbolAddress((void**)&kp,   g_kp);
    cudaGetSymbolAddress((void**)&v,    g_v);
    cudaGetSymbolAddress((void**)&vt,   g_vt);
    cudaGetSymbolAddress((void**)&op,   g_op);
    cudaGetSymbolAddress((void**)&proj, g_proj);

    cudaFuncSetAttribute(gemm_qkv,  cudaFuncAttributeMaxDynamicSharedMemorySize, GPSMEM);
    cudaFuncSetAttribute(gemm_wo,   cudaFuncAttributeMaxDynamicSharedMemorySize, GPSMEM);
    cudaFuncSetAttribute(flash_mma, cudaFuncAttributeMaxDynamicSharedMemorySize, FA_SMEM);

    pack_x<<<2048, 256>>>((const float4*)x, (uint4*)xp);
    pack_w<<<dim3(512, 4), 256>>>(Wq, Wk, Wv, Wo, wp);
    gemm_qkv<<<dim3(Dm / BN, Mtot / BM, 3), 256, GPSMEM>>>(xp, wp, qp, kp, v);
    vtrans<<<dim3(Sq / 64, Hh, Bsz), 256>>>(v, vt);
    flash_mma<<<dim3(Sq / 128, Hh, Bsz), 256, FA_SMEM>>>(qp, kp, vt, op);
    gemm_wo<<<dim3(Dm / BN, Mtot / BM), 256, GPSMEM>>>(op, wp, proj);
    ln_quantum<<<Mtot, 256>>>(x, proj, g1, b1, Win, b_in, Wout, b_out, ry, g2, b2, out);
}

// round 15
// speedup vs baseline: 1.0655x; 1.0655x over previous
#include <cuda_runtime.h>
#include <math.h>
#include <cstdint>

#define Bsz   2
#define Sq    2048
#define Dm    1024
#define Hh    16
#define Mtot  4096
#define DIMq  256
#define EPSf  1e-5f
#define LOG2E 1.44269504088896f

// ---------------- scratch ----------------
__device__ uint32_t g_xp[Mtot * 512];
__device__ uint32_t g_wp[4 * 1024 * 512];
__device__ uint32_t g_qp[Mtot * 512];
__device__ uint32_t g_kp[Mtot * 512];
__device__ uint32_t g_vt[Mtot * 512];   // V transposed+packed (written by V-GEMM epilogue)
__device__ uint32_t g_op[Mtot * 512];
__device__ float    g_proj[Mtot * Dm];

// ======================= helpers =======================
__device__ __forceinline__ uint32_t smem_to_u32(const void* p) {
    uint32_t a;
    asm("{ .reg .u64 t; cvta.to.shared.u64 t, %1; cvt.u32.u64 %0, t; }" : "=r"(a) : "l"(p));
    return a;
}
__device__ __forceinline__ void cp16(uint32_t sm, const void* g) {
    asm volatile("cp.async.cg.shared.global [%0], [%1], 16;" :: "r"(sm), "l"(g));
}
__device__ __forceinline__ void cp_commit() {
    asm volatile("cp.async.commit_group;");
}
template <int N>
__device__ __forceinline__ void cp_wait() {
    asm volatile("cp.async.wait_group %0;" :: "n"(N));
}
__device__ __forceinline__ uint32_t f2bf2(float lo, float hi) {
    uint32_t r;
    asm("cvt.rn.bf16x2.f32 %0, %1, %2;" : "=r"(r) : "f"(hi), "f"(lo));
    return r;
}
__device__ __forceinline__ void mma_bf16(float c[4], const uint32_t a[4], const uint32_t b[2]) {
    asm volatile(
        "mma.sync.aligned.m16n8k16.row.col.f32.bf16.bf16.f32 "
        "{%0,%1,%2,%3}, {%4,%5,%6,%7}, {%8,%9}, {%0,%1,%2,%3};"
        : "+f"(c[0]), "+f"(c[1]), "+f"(c[2]), "+f"(c[3])
        : "r"(a[0]), "r"(a[1]), "r"(a[2]), "r"(a[3]), "r"(b[0]), "r"(b[1]));
}

// ================= pack x -> bf16x2 =================
__global__ __launch_bounds__(256) void pack_x(const float4* __restrict__ x4,
                                              uint4* __restrict__ xp4)
{
    int idx = blockIdx.x * 256 + threadIdx.x;
    float4 a = x4[idx * 2];
    float4 b = x4[idx * 2 + 1];
    uint4 w;
    w.x = f2bf2(a.x, a.y); w.y = f2bf2(a.z, a.w);
    w.z = f2bf2(b.x, b.y); w.w = f2bf2(b.z, b.w);
    xp4[idx] = w;
}

// ================= pack 4 weights -> bf16x2 =================
__global__ __launch_bounds__(256) void pack_w(const float* __restrict__ W0,
                                              const float* __restrict__ W1,
                                              const float* __restrict__ W2,
                                              const float* __restrict__ W3,
                                              uint32_t* __restrict__ wp)
{
    const int z = blockIdx.y;
    const float* W = (z == 0) ? W0 : (z == 1) ? W1 : (z == 2) ? W2 : W3;
    const float4* w4 = reinterpret_cast<const float4*>(W);
    uint4* o4 = reinterpret_cast<uint4*>(wp + (size_t)z * 1024 * 512);
    int idx = blockIdx.x * 256 + threadIdx.x;
    float4 a = w4[idx * 2];
    float4 b = w4[idx * 2 + 1];
    uint4 w;
    w.x = f2bf2(a.x, a.y); w.y = f2bf2(a.z, a.w);
    w.z = f2bf2(b.x, b.y); w.w = f2bf2(b.z, b.w);
    o4[idx] = w;
}

// ============ bf16 GEMM, BOTH operands packed ============
// outmode 0: fp32 -> Cf
// outmode 1: pack bf16x2 * scale -> Cp (row-major packed)
// outmode 2: V transposed+packed -> Cp as vt[((b*Hh+h)*64+d)*1024 + tokenpair]
#define BM 128
#define BN 256
#define PAW 20
#define PBW 20
#define PA_STAGE_B (BM * PAW * 4)
#define PB_STAGE_B (BN * PBW * 4)
#define GPSMEM (3 * (PA_STAGE_B + PB_STAGE_B))
#define NKT (Dm / 32)

__device__ __forceinline__ void gemm_pp(const uint32_t* __restrict__ Ap,
                                        const uint32_t* __restrict__ Wp,
                                        float* __restrict__ Cf,
                                        uint32_t* __restrict__ Cp,
                                        int outmode, float scale,
                                        char* gsm)
{
    const uint32_t usm = smem_to_u32(gsm);
    const uint32_t usmA = usm;
    const uint32_t usmB = usm + 3 * PA_STAGE_B;

    const int tid  = threadIdx.x;
    const int wid  = tid >> 5;
    const int lane = tid & 31;
    const int grp  = lane >> 2;
    const int tig  = lane & 3;
    const int wm   = wid >> 2;
    const int wn   = wid & 3;

    const int aRow0 = blockIdx.y * BM;
    const int bRow0 = blockIdx.x * BN;

    int aSm[2], aGm[2], bSm[4], bGm[4];
#pragma unroll
    for (int i = 0; i < 2; i++) {
        int e = tid + (i << 8);
        int r = e >> 2, c4 = (e & 3) << 2;
        aSm[i] = (r * PAW + c4) * 4;
        aGm[i] = r * 512 + c4;
    }
#pragma unroll
    for (int i = 0; i < 4; i++) {
        int e = tid + (i << 8);
        int r = e >> 2, c4 = (e & 3) << 2;
        bSm[i] = (r * PBW + c4) * 4;
        bGm[i] = r * 512 + c4;
    }
    const uint32_t* gA = Ap + (size_t)aRow0 * 512;
    const uint32_t* gB = Wp + (size_t)bRow0 * 512;

    float acc[4][8][4];
#pragma unroll
    for (int im = 0; im < 4; im++)
#pragma unroll
        for (int jn = 0; jn < 8; jn++)
#pragma unroll
            for (int t = 0; t < 4; t++) acc[im][jn][t] = 0.f;

#pragma unroll
    for (int p = 0; p < 2; p++) {
        uint32_t sa = usmA + p * PA_STAGE_B;
        uint32_t sb = usmB + p * PB_STAGE_B;
        const uint32_t* ka = gA + p * 16;
        const uint32_t* kb = gB + p * 16;
#pragma unroll
        for (int i = 0; i < 2; i++) cp16(sa + aSm[i], ka + aGm[i]);
#pragma unroll
        for (int i = 0; i < 4; i++) cp16(sb + bSm[i], kb + bGm[i]);
        cp_commit();
    }

    for (int kt = 0; kt < NKT; kt++) {
        cp_wait<1>();
        __syncthreads();

        if (kt + 2 < NKT) {
            int s = (kt + 2) % 3;
            uint32_t sa = usmA + s * PA_STAGE_B;
            uint32_t sb = usmB + s * PB_STAGE_B;
            const uint32_t* ka = gA + (kt + 2) * 16;
            const uint32_t* kb = gB + (kt + 2) * 16;
#pragma unroll
            for (int i = 0; i < 2; i++) cp16(sa + aSm[i], ka + aGm[i]);
#pragma unroll
            for (int i = 0; i < 4; i++) cp16(sb + bSm[i], kb + bGm[i]);
        }
        cp_commit();

        const uint32_t* Asp = (const uint32_t*)(gsm + (kt % 3) * PA_STAGE_B);
        const uint32_t* Bsp = (const uint32_t*)(gsm + 3 * PA_STAGE_B + (kt % 3) * PB_STAGE_B);

#pragma unroll
        for (int k16 = 0; k16 < 2; k16++) {
            const int pi = k16 * 8 + tig;
            uint32_t afr[4][4], bfr[8][2];
#pragma unroll
            for (int im = 0; im < 4; im++) {
                int row = wm * 64 + im * 16 + grp;
                afr[im][0] = Asp[row * PAW + pi];
                afr[im][1] = Asp[(row + 8) * PAW + pi];
                afr[im][2] = Asp[row * PAW + pi + 4];
                afr[im][3] = Asp[(row + 8) * PAW + pi + 4];
            }
#pragma unroll
            for (int jn = 0; jn < 8; jn++) {
                int brow = wn * 64 + jn * 8 + grp;
                bfr[jn][0] = Bsp[brow * PBW + pi];
                bfr[jn][1] = Bsp[brow * PBW + pi + 4];
            }
#pragma unroll
            for (int im = 0; im < 4; im++)
#pragma unroll
                for (int jn = 0; jn < 8; jn++)
                    mma_bf16(acc[im][jn], afr[im], bfr[jn]);
        }
    }

    const int rowBase = aRow0 + wm * 64;
    const int colBase = bRow0 + wn * 64;
    if (outmode == 0) {
#pragma unroll
        for (int im = 0; im < 4; im++) {
            int r0 = rowBase + im * 16 + grp;
#pragma unroll
            for (int jn = 0; jn < 8; jn++) {
                int col = colBase + jn * 8 + 2 * tig;
                float2 v01 = make_float2(acc[im][jn][0], acc[im][jn][1]);
                float2 v23 = make_float2(acc[im][jn][2], acc[im][jn][3]);
                *reinterpret_cast<float2*>(Cf + (size_t)r0 * Dm + col) = v01;
                *reinterpret_cast<float2*>(Cf + (size_t)(r0 + 8) * Dm + col) = v23;
            }
        }
    } else if (outmode == 1) {
#pragma unroll
        for (int im = 0; im < 4; im++) {
            int r0 = rowBase + im * 16 + grp;
#pragma unroll
            for (int jn = 0; jn < 8; jn++) {
                int col = colBase + jn * 8 + 2 * tig;
                Cp[(size_t)r0 * 512 + (col >> 1)] =
                    f2bf2(acc[im][jn][0] * scale, acc[im][jn][1] * scale);
                Cp[(size_t)(r0 + 8) * 512 + (col >> 1)] =
                    f2bf2(acc[im][jn][2] * scale, acc[im][jn][3] * scale);
            }
        }
    } else {
        // V epilogue: exchange adjacent token rows (grp ^ 1 via lane^4),
        // even-grp lanes emit transposed packed pairs. Bit-identical to vtrans.
#pragma unroll
        for (int im = 0; im < 4; im++) {
            int r0 = rowBase + im * 16 + grp;     // token (even when grp even)
#pragma unroll
            for (int jn = 0; jn < 8; jn++) {
                int col = colBase + jn * 8 + 2 * tig;
                float o0 = acc[im][jn][0], o1 = acc[im][jn][1];
                float o2 = acc[im][jn][2], o3 = acc[im][jn][3];
                float p0 = __shfl_xor_sync(0xffffffffu, o0, 4);
                float p1 = __shfl_xor_sync(0xffffffffu, o1, 4);
                float p2 = __shfl_xor_sync(0xffffffffu, o2, 4);
                float p3 = __shfl_xor_sync(0xffffffffu, o3, 4);
                if (!(grp & 1)) {
                    int bI = r0 >> 11;
                    int tp0 = (r0 & 2047) >> 1;
                    int tp8 = ((r0 + 8) & 2047) >> 1;
                    int h = col >> 6, d = col & 63;
                    uint32_t* base = Cp + (((size_t)(bI * Hh + h) * 64 + d) << 10);
                    base[tp0]        = f2bf2(o0, p0);
                    base[1024 + tp0] = f2bf2(o1, p1);
                    base[tp8]        = f2bf2(o2, p2);
                    base[1024 + tp8] = f2bf2(o3, p3);
                }
            }
        }
    }
}

__global__ __launch_bounds__(256, 1) void gemm_qkv(const uint32_t* __restrict__ Ap,
                                                   const uint32_t* __restrict__ Wp,
                                                   uint32_t* __restrict__ Qp,
                                                   uint32_t* __restrict__ Kp,
                                                   uint32_t* __restrict__ Vt)
{
    extern __shared__ __align__(16) char gsm[];
    const int z = blockIdx.z;
    if (z == 0)      gemm_pp(Ap, Wp,                  nullptr, Qp, 1, 0.125f * LOG2E, gsm);
    else if (z == 1) gemm_pp(Ap, Wp + 1024 * 512,     nullptr, Kp, 1, 1.f, gsm);
    else             gemm_pp(Ap, Wp + 2 * 1024 * 512, nullptr, Vt, 2, 1.f, gsm);
}

__global__ __launch_bounds__(256, 1) void gemm_wo(const uint32_t* __restrict__ Ap,
                                                  const uint32_t* __restrict__ Wp,
                                                  float* __restrict__ C)
{
    extern __shared__ __align__(16) char gsm[];
    gemm_pp(Ap, Wp + 3 * 1024 * 512, C, nullptr, 0, 1.f, gsm);
}

// ============ Flash attention (R13-proven: 256 Q rows, all packed) ==========
#define PPW   36
#define KPW   36
#define QP_OFF 0
#define PP_OFF (256 * PPW)
#define KP_OFF (2 * 256 * PPW)
#define KP_STRIDE (64 * KPW)
#define VP_OFF (KP_OFF + 3 * KP_STRIDE)
#define FA_SMEM ((VP_OFF + 3 * KP_STRIDE) * 4)
#define NKV (Sq / 64)

__global__ __launch_bounds__(256, 1) void flash_mma(const uint32_t* __restrict__ qpg,
                                                    const uint32_t* __restrict__ kpg,
                                                    const uint32_t* __restrict__ vtg_all,
                                                    uint32_t* __restrict__ op)
{
    extern __shared__ __align__(16) uint32_t fsu[];
    const uint32_t usm = smem_to_u32(fsu);
    uint32_t* qp = fsu + QP_OFF;
    uint32_t* pp = fsu + PP_OFF;
    const uint32_t* kp = fsu + KP_OFF;
    const uint32_t* vp = fsu + VP_OFF;

    const int tid  = threadIdx.x;
    const int wid  = tid >> 5;
    const int lane = tid & 31;
    const int grp  = lane >> 2;
    const int tig  = lane & 3;

    const int b  = blockIdx.z;
    const int h  = blockIdx.y;
    const int q0 = blockIdx.x << 8;

    const uint32_t* qg  = qpg + (size_t)(b * Sq + q0) * 512 + h * 32;
    const uint32_t* kg  = kpg + (size_t)(b * Sq) * 512 + h * 32;
    const uint32_t* vtg = vtg_all + ((size_t)(b * Hh + h) * 64) * 1024;

    {
#pragma unroll
        for (int i = 0; i < 2; i++) {
            int e = tid + (i << 8);
            int r = e >> 3, c4 = (e & 7) << 2;
            cp16(usm + (KP_OFF + r * KPW + c4) * 4, kg + (size_t)r * 512 + c4);
            cp16(usm + (VP_OFF + r * KPW + c4) * 4, vtg + (size_t)r * 1024 + c4);
        }
#pragma unroll
        for (int i = 0; i < 8; i++) {
            int e = tid + (i << 8);
            int r = e >> 3, c4 = (e & 7) << 2;
            cp16(usm + (QP_OFF + r * PPW + c4) * 4, qg + (size_t)r * 512 + c4);
        }
        cp_commit();
#pragma unroll
        for (int i = 0; i < 2; i++) {
            int e = tid + (i << 8);
            int r = e >> 3, c4 = (e & 7) << 2;
            cp16(usm + (KP_OFF + KP_STRIDE + r * KPW + c4) * 4, kg + (size_t)(64 + r) * 512 + c4);
            cp16(usm + (VP_OFF + KP_STRIDE + r * KPW + c4) * 4, vtg + (size_t)r * 1024 + 32 + c4);
        }
        cp_commit();
    }

    const int lr0 = wid * 32 + grp;
    const int lr1 = lr0 + 16;

    float m00 = -1e30f, m01 = -1e30f, m10 = -1e30f, m11 = -1e30f;
    float l00 = 0.f, l01 = 0.f, l10 = 0.f, l11 = 0.f;
    float oac0[8][4], oac1[8][4];
#pragma unroll
    for (int jd = 0; jd < 8; jd++)
#pragma unroll
        for (int t = 0; t < 4; t++) { oac0[jd][t] = 0.f; oac1[jd][t] = 0.f; }

    for (int it = 0; it < NKV; it++) {
        cp_wait<1>();
        __syncthreads();

        if (it + 2 < NKV) {
            int s = (it + 2) % 3;
            int kv0 = (it + 2) << 6;
            int kv32 = (it + 2) << 5;
#pragma unroll
            for (int i = 0; i < 2; i++) {
                int e = tid + (i << 8);
                int r = e >> 3, c4 = (e & 7) << 2;
                cp16(usm + (KP_OFF + s * KP_STRIDE + r * KPW + c4) * 4,
                     kg + (size_t)(kv0 + r) * 512 + c4);
                cp16(usm + (VP_OFF + s * KP_STRIDE + r * KPW + c4) * 4,
                     vtg + (size_t)r * 1024 + kv32 + c4);
            }
        }
        cp_commit();

        const uint32_t* Kb = kp + (it % 3) * KP_STRIDE;
        const uint32_t* Vb = vp + (it % 3) * KP_STRIDE;

        float sac0[8][4], sac1[8][4];
#pragma unroll
        for (int jn = 0; jn < 8; jn++)
#pragma unroll
            for (int t = 0; t < 4; t++) { sac0[jn][t] = 0.f; sac1[jn][t] = 0.f; }
#pragma unroll
        for (int k16 = 0; k16 < 4; k16++) {
            const int pi = k16 * 8 + tig;
            uint32_t bfr[8][2];
#pragma unroll
            for (int jn = 0; jn < 8; jn++) {
                int krow = jn * 8 + grp;
                bfr[jn][0] = Kb[krow * KPW + pi];
                bfr[jn][1] = Kb[krow * KPW + pi + 4];
            }
            uint32_t af0[4], af1[4];
            af0[0] = qp[lr0 * PPW + pi];       af0[1] = qp[(lr0 + 8) * PPW + pi];
            af0[2] = qp[lr0 * PPW + pi + 4];   af0[3] = qp[(lr0 + 8) * PPW + pi + 4];
            af1[0] = qp[lr1 * PPW + pi];       af1[1] = qp[(lr1 + 8) * PPW + pi];
            af1[2] = qp[lr1 * PPW + pi + 4];   af1[3] = qp[(lr1 + 8) * PPW + pi + 4];
#pragma unroll
            for (int jn = 0; jn < 8; jn++) {
                mma_bf16(sac0[jn], af0, bfr[jn]);
                mma_bf16(sac1[jn], af1, bfr[jn]);
            }
        }

        {
            float mx0 = -1e30f, mx1 = -1e30f;
#pragma unroll
            for (int jn = 0; jn < 8; jn++) {
                mx0 = fmaxf(mx0, fmaxf(sac0[jn][0], sac0[jn][1]));
                mx1 = fmaxf(mx1, fmaxf(sac0[jn][2], sac0[jn][3]));
            }
            mx0 = fmaxf(mx0, __shfl_xor_sync(0xffffffffu, mx0, 1));
            mx0 = fmaxf(mx0, __shfl_xor_sync(0xffffffffu, mx0, 2));
            mx1 = fmaxf(mx1, __shfl_xor_sync(0xffffffffu, mx1, 1));
            mx1 = fmaxf(mx1, __shfl_xor_sync(0xffffffffu, mx1, 2));
            float mn0 = fmaxf(m00, mx0), mn1 = fmaxf(m01, mx1);
            float al0 = exp2f(m00 - mn0), al1 = exp2f(m01 - mn1);
            float sum0 = 0.f, sum1 = 0.f;
#pragma unroll
            for (int jn = 0; jn < 8; jn++) {
                float p00 = exp2f(sac0[jn][0] - mn0);
                float p01 = exp2f(sac0[jn][1] - mn0);
                float p10 = exp2f(sac0[jn][2] - mn1);
                float p11 = exp2f(sac0[jn][3] - mn1);
                int ci = jn * 4 + tig;
                pp[lr0 * PPW + ci]       = f2bf2(p00, p01);
                pp[(lr0 + 8) * PPW + ci] = f2bf2(p10, p11);
                sum0 += p00 + p01;  sum1 += p10 + p11;
            }
            sum0 += __shfl_xor_sync(0xffffffffu, sum0, 1);
            sum0 += __shfl_xor_sync(0xffffffffu, sum0, 2);
            sum1 += __shfl_xor_sync(0xffffffffu, sum1, 1);
            sum1 += __shfl_xor_sync(0xffffffffu, sum1, 2);
            l00 = l00 * al0 + sum0;  m00 = mn0;
            l01 = l01 * al1 + sum1;  m01 = mn1;
#pragma unroll
            for (int jd = 0; jd < 8; jd++) {
                oac0[jd][0] *= al0; oac0[jd][1] *= al0;
                oac0[jd][2] *= al1; oac0[jd][3] *= al1;
            }
        }
        {
            float mx0 = -1e30f, mx1 = -1e30f;
#pragma unroll
            for (int jn = 0; jn < 8; jn++) {
                mx0 = fmaxf(mx0, fmaxf(sac1[jn][0], sac1[jn][1]));
                mx1 = fmaxf(mx1, fmaxf(sac1[jn][2], sac1[jn][3]));
            }
            mx0 = fmaxf(mx0, __shfl_xor_sync(0xffffffffu, mx0, 1));
            mx0 = fmaxf(mx0, __shfl_xor_sync(0xffffffffu, mx0, 2));
            mx1 = fmaxf(mx1, __shfl_xor_sync(0xffffffffu, mx1, 1));
            mx1 = fmaxf(mx1, __shfl_xor_sync(0xffffffffu, mx1, 2));
            float mn0 = fmaxf(m10, mx0), mn1 = fmaxf(m11, mx1);
            float al0 = exp2f(m10 - mn0), al1 = exp2f(m11 - mn1);
            float sum0 = 0.f, sum1 = 0.f;
#pragma unroll
            for (int jn = 0; jn < 8; jn++) {
                float p00 = exp2f(sac1[jn][0] - mn0);
                float p01 = exp2f(sac1[jn][1] - mn0);
                float p10 = exp2f(sac1[jn][2] - mn1);
                float p11 = exp2f(sac1[jn][3] - mn1);
                int ci = jn * 4 + tig;
                pp[lr1 * PPW + ci]       = f2bf2(p00, p01);
                pp[(lr1 + 8) * PPW + ci] = f2bf2(p10, p11);
                sum0 += p00 + p01;  sum1 += p10 + p11;
            }
            sum0 += __shfl_xor_sync(0xffffffffu, sum0, 1);
            sum0 += __shfl_xor_sync(0xffffffffu, sum0, 2);
            sum1 += __shfl_xor_sync(0xffffffffu, sum1, 1);
            sum1 += __shfl_xor_sync(0xffffffffu, sum1, 2);
            l10 = l10 * al0 + sum0;  m10 = mn0;
            l11 = l11 * al1 + sum1;  m11 = mn1;
#pragma unroll
            for (int jd = 0; jd < 8; jd++) {
                oac1[jd][0] *= al0; oac1[jd][1] *= al0;
                oac1[jd][2] *= al1; oac1[jd][3] *= al1;
            }
        }
        __syncwarp();

#pragma unroll
        for (int k16 = 0; k16 < 4; k16++) {
            const int pi = k16 * 8 + tig;
            uint32_t bfr[8][2];
#pragma unroll
            for (int jd = 0; jd < 8; jd++) {
                int dcol = jd * 8 + grp;
                bfr[jd][0] = Vb[dcol * KPW + pi];
                bfr[jd][1] = Vb[dcol * KPW + pi + 4];
            }
            uint32_t af0[4], af1[4];
            af0[0] = pp[lr0 * PPW + pi];       af0[1] = pp[(lr0 + 8) * PPW + pi];
            af0[2] = pp[lr0 * PPW + pi + 4];   af0[3] = pp[(lr0 + 8) * PPW + pi + 4];
            af1[0] = pp[lr1 * PPW + pi];       af1[1] = pp[(lr1 + 8) * PPW + pi];
            af1[2] = pp[lr1 * PPW + pi + 4];   af1[3] = pp[(lr1 + 8) * PPW + pi + 4];
#pragma unroll
            for (int jd = 0; jd < 8; jd++) {
                mma_bf16(oac0[jd], af0, bfr[jd]);
                mma_bf16(oac1[jd], af1, bfr[jd]);
            }
        }
    }

    {
        float inv0 = 1.f / l00, inv1 = 1.f / l01;
        uint32_t* og  = op + (size_t)(b * Sq + q0 + lr0) * 512 + h * 32;
        uint32_t* og8 = og + (size_t)8 * 512;
#pragma unroll
        for (int jd = 0; jd < 8; jd++) {
            og[jd * 4 + tig]  = f2bf2(oac0[jd][0] * inv0, oac0[jd][1] * inv0);
            og8[jd * 4 + tig] = f2bf2(oac0[jd][2] * inv1, oac0[jd][3] * inv1);
        }
    }
    {
        float inv0 = 1.f / l10, inv1 = 1.f / l11;
        uint32_t* og  = op + (size_t)(b * Sq + q0 + lr1) * 512 + h * 32;
        uint32_t* og8 = og + (size_t)8 * 512;
#pragma unroll
        for (int jd = 0; jd < 8; jd++) {
            og[jd * 4 + tig]  = f2bf2(oac1[jd][0] * inv0, oac1[jd][1] * inv0);
            og8[jd * 4 + tig] = f2bf2(oac1[jd][2] * inv1, oac1[jd][3] * inv1);
        }
    }
}

// ========= fused LN1 + quantum FFN + LN2 (R11-proven) =========
__global__ __launch_bounds__(256) void ln_quantum(const float* __restrict__ x,
                                                  const float* __restrict__ proj,
                                                  const float* __restrict__ g1,
                                                  const float* __restrict__ b1,
                                                  const float* __restrict__ Win,
                                                  const float* __restrict__ b_in,
                                                  const float* __restrict__ Wout,
                                                  const float* __restrict__ b_out,
                                                  const float* __restrict__ ry,
                                                  const float* __restrict__ g2,
                                                  const float* __restrict__ b2,
                                                  float* __restrict__ out)
{
    const int row = blockIdx.x;
    const int tid = threadIdx.x;
    const int lane = tid & 31, wid = tid >> 5;
    const float* px = x + (size_t)row * Dm;
    const float* pprj = proj + (size_t)row * Dm;

    __shared__ float redw[64];
    __shared__ float angs[8];
    __shared__ float ezs[8];
    __shared__ float2 st[2][DIMq];

    float xv[4];
    {
        float yv[4], sum = 0.f, sq = 0.f;
#pragma unroll
        for (int j = 0; j < 4; j++) {
            int d = tid + (j << 8);
            float t = px[d] + pprj[d];
            yv[j] = t; sum += t; sq = fmaf(t, t, sq);
        }
#pragma unroll
        for (int off = 16; off; off >>= 1) {
            sum += __shfl_xor_sync(0xffffffffu, sum, off);
            sq  += __shfl_xor_sync(0xffffffffu, sq, off);
        }
        if (lane == 0) { redw[wid] = sum; redw[8 + wid] = sq; }
        __syncthreads();
        float tsum = 0.f, tsq = 0.f;
#pragma unroll
        for (int w = 0; w < 8; w++) { tsum += redw[w]; tsq += redw[8 + w]; }
        float mean = tsum * (1.f / 1024.f);
        float var  = tsq * (1.f / 1024.f) - mean * mean;
        float rstd = rsqrtf(var + EPSf);
#pragma unroll
        for (int j = 0; j < 4; j++) {
            int d = tid + (j << 8);
            xv[j] = (yv[j] - mean) * rstd * g1[d] + b1[d];
        }
        __syncthreads();
    }

    float accq[8] = {0, 0, 0, 0, 0, 0, 0, 0};
#pragma unroll
    for (int j = 0; j < 4; j++) {
        int d = tid + (j << 8);
#pragma unroll
        for (int qq = 0; qq < 8; qq++)
            accq[qq] = fmaf(xv[j], Win[qq * Dm + d], accq[qq]);
    }
#pragma unroll
    for (int qq = 0; qq < 8; qq++) {
        float vsum = accq[qq];
#pragma unroll
        for (int off = 16; off; off >>= 1)
            vsum += __shfl_xor_sync(0xffffffffu, vsum, off);
        if (lane == 0) redw[wid * 8 + qq] = vsum;
    }
    __syncthreads();
    if (tid < 8) {
        float s = b_in[tid];
#pragma unroll
        for (int w = 0; w < 8; w++) s += redw[w * 8 + tid];
        angs[tid] = s * 0.5f;
    }
    st[0][tid] = make_float2(tid == 0 ? 1.f : 0.f, 0.f);
    __syncthreads();

    int curb = 0;
#pragma unroll
    for (int k = 0; k < 4; k++) {
        int m1 = 1 << (7 - 2 * k);
        int m2 = m1 >> 1;
        float s1, c1, s2, c2;
        __sincosf(angs[2 * k], &s1, &c1);
        __sincosf(angs[2 * k + 1], &s2, &c2);
        float cc = c1 * c2, cs = c1 * s2, sc = s1 * c2, ss = s1 * s2;
        float2 x0  = st[curb][tid];
        float2 x1  = st[curb][tid ^ m1];
        float2 x2  = st[curb][tid ^ m2];
        float2 x12 = st[curb][tid ^ (m1 | m2)];
        float nr = cc * x0.x + cs * x2.y + sc * x1.y - ss * x12.x;
        float ni = cc * x0.y - cs * x2.x - sc * x1.x - ss * x12.y;
        st[curb ^ 1][tid] = make_float2(nr, ni);
        curb ^= 1;
        __syncthreads();
    }
#pragma unroll
    for (int k = 0; k < 4; k++) {
        int m1 = 1 << (7 - 2 * k);
        int m2 = m1 >> 1;
        float s1, c1, s2, c2;
        __sincosf(ry[2 * k] * 0.5f, &s1, &c1);
        __sincosf(ry[2 * k + 1] * 0.5f, &s2, &c2);
        float sg1 = (tid & m1) ? s1 : -s1;
        float sg2 = (tid & m2) ? s2 : -s2;
        float cc = c1 * c2, a2 = c1 * sg2, a1 = sg1 * c2, a12 = sg1 * sg2;
        float2 x0  = st[curb][tid];
        float2 x1  = st[curb][tid ^ m1];
        float2 x2  = st[curb][tid ^ m2];
        float2 x12 = st[curb][tid ^ (m1 | m2)];
        float nr = cc * x0.x + a2 * x2.x + a1 * x1.x + a12 * x12.x;
        float ni = cc * x0.y + a2 * x2.y + a1 * x1.y + a12 * x12.y;
        st[curb ^ 1][tid] = make_float2(nr, ni);
        curb ^= 1;
        __syncthreads();
    }
    int src = tid;
#pragma unroll
    for (int c = 6; c >= 0; c--) {
        int cmask = 1 << (7 - c);
        int tmask = cmask >> 1;
        if (src & cmask) src ^= tmask;
    }
    float2 fa = st[curb][src];
    float p = fa.x * fa.x + fa.y * fa.y;

#pragma unroll
    for (int w = 0; w < 8; w++) {
        float vsum = ((tid >> (7 - w)) & 1) ? -p : p;
#pragma unroll
        for (int off = 16; off; off >>= 1)
            vsum += __shfl_xor_sync(0xffffffffu, vsum, off);
        if (lane == 0) redw[wid * 8 + w] = vsum;
    }
    __syncthreads();
    if (tid < 8) {
        float s = 0.f;
#pragma unroll
        for (int w = 0; w < 8; w++) s += redw[w * 8 + tid];
        ezs[tid] = s;
    }
    __syncthreads();
    float e[8];
#pragma unroll
    for (int qq = 0; qq < 8; qq++) e[qq] = ezs[qq];

    float y[4], sum = 0.f, sq = 0.f;
#pragma unroll
    for (int j = 0; j < 4; j++) {
        int d = tid + (j << 8);
        const float4* wrow = reinterpret_cast<const float4*>(Wout + (size_t)d * 8);
        float4 w0 = wrow[0], w1 = wrow[1];
        float acc = b_out[d];
        acc = fmaf(e[0], w0.x, acc); acc = fmaf(e[1], w0.y, acc);
        acc = fmaf(e[2], w0.z, acc); acc = fmaf(e[3], w0.w, acc);
        acc = fmaf(e[4], w1.x, acc); acc = fmaf(e[5], w1.y, acc);
        acc = fmaf(e[6], w1.z, acc); acc = fmaf(e[7], w1.w, acc);
        acc = fmaxf(acc, 0.f);
        float yv = xv[j] + acc;
        y[j] = yv; sum += yv; sq = fmaf(yv, yv, sq);
    }
    __syncthreads();
#pragma unroll
    for (int off = 16; off; off >>= 1) {
        sum += __shfl_xor_sync(0xffffffffu, sum, off);
        sq  += __shfl_xor_sync(0xffffffffu, sq, off);
    }
    if (lane == 0) { redw[wid] = sum; redw[8 + wid] = sq; }
    __syncthreads();
    float tsum = 0.f, tsq = 0.f;
#pragma unroll
    for (int w = 0; w < 8; w++) { tsum += redw[w]; tsq += redw[8 + w]; }
    float mean = tsum * (1.f / 1024.f);
    float var  = tsq * (1.f / 1024.f) - mean * mean;
    float rstd = rsqrtf(var + EPSf);
#pragma unroll
    for (int j = 0; j < 4; j++) {
        int d = tid + (j << 8);
        out[(size_t)row * Dm + d] = (y[j] - mean) * rstd * g2[d] + b2[d];
    }
}

// ---------------- launch ----------------
extern "C" void kernel_launch(void* const* d_in, const int* in_sizes, int n_in,
                              void* d_out, int out_size)
{
    const float* x     = (const float*)d_in[0];
    const float* Wq    = (const float*)d_in[1];
    const float* Wk    = (const float*)d_in[2];
    const float* Wv    = (const float*)d_in[3];
    const float* Wo    = (const float*)d_in[4];
    const float* g1    = (const float*)d_in[5];
    const float* b1    = (const float*)d_in[6];
    const float* g2    = (const float*)d_in[7];
    const float* b2    = (const float*)d_in[8];
    const float* Win   = (const float*)d_in[9];
    const float* b_in  = (const float*)d_in[10];
    const float* Wout  = (const float*)d_in[11];
    const float* b_out = (const float*)d_in[12];
    const float* ry    = (const float*)d_in[13];
    float* out = (float*)d_out;

    uint32_t *xp, *wp, *qp, *kp, *vt, *op;
    float *proj;
    cudaGetSymbolAddress((void**)&xp,   g_xp);
    cudaGetSymbolAddress((void**)&wp,   g_wp);
    cudaGetSymbolAddress((void**)&qp,   g_qp);
    cudaGetSymbolAddress((void**)&kp,   g_kp);
    cudaGetSymbolAddress((void**)&vt,   g_vt);
    cudaGetSymbolAddress((void**)&op,   g_op);
    cudaGetSymbolAddress((void**)&proj, g_proj);

    cudaFuncSetAttribute(gemm_qkv,  cudaFuncAttributeMaxDynamicSharedMemorySize, GPSMEM);
    cudaFuncSetAttribute(gemm_wo,   cudaFuncAttributeMaxDynamicSharedMemorySize, GPSMEM);
    cudaFuncSetAttribute(flash_mma, cudaFuncAttributeMaxDynamicSharedMemorySize, FA_SMEM);

    pack_x<<<2048, 256>>>((const float4*)x, (uint4*)xp);
    pack_w<<<dim3(512, 4), 256>>>(Wq, Wk, Wv, Wo, wp);
    gemm_qkv<<<dim3(Dm / BN, Mtot / BM, 3), 256, GPSMEM>>>(xp, wp, qp, kp, vt);
    flash_mma<<<dim3(Sq / 256, Hh, Bsz), 256, FA_SMEM>>>(qp, kp, vt, op);
    gemm_wo<<<dim3(Dm / BN, Mtot / BM), 256, GPSMEM>>>(op, wp, proj);
    ln_quantum<<<Mtot, 256>>>(x, proj, g1, b1, Win, b_in, Wout, b_out, ry, g2, b2, out);
}